// round 9
// baseline (speedup 1.0000x reference)
#include <cuda_runtime.h>

// Involution: B=4, H=W=56, C=256, Cr=64, G=16, Cg=16, K=7, pad=3
// Round 8: 4 CTAs/SM (<=64 regs, 55.5KB smem), 1 group/iter, kh-major kg rows,
// B4 || halo-prefetch, 64px rs blocks.

#define HH 56
#define WWD 56
#define CC 256
#define CR 64
#define CGC 16
#define KKT 49
#define NPIXT 12544
#define TILE 8
#define HALO 14
#define NPOS 196
#define RSPD 68
#define KGR 56

__device__ __align__(16) float g_wsT[16 * KKT * CR];   // [g*49+k][d]
__device__ __align__(16) float g_rs[(size_t)NPIXT * CR];

// ------------------------------------------------ rs GEMM (+ overlapped transpose)
#define RPXB 64
#define NRSBLK 196
struct SmemR {
    float xs[RPXB][68];   // 17408 B
    float ws[CR][CR];     // 16384 B
};

__global__ __launch_bounds__(256)
void rs_kernel(const float* __restrict__ x,
               const float* __restrict__ wr,
               const float* __restrict__ gamma,
               const float* __restrict__ beta,
               const float* __restrict__ mean,
               const float* __restrict__ var,
               const float* __restrict__ wspan) {
    extern __shared__ __align__(16) float smr[];
    SmemR& s = *reinterpret_cast<SmemR*>(smr);
    const int t = threadIdx.x;

    if (blockIdx.x >= NRSBLK) {
        __shared__ float ttile[32][33];
        const int bt = blockIdx.x - NRSBLK;          // 0..49
        const int tx = t & 31, ty8 = t >> 5;
        const int gk0 = (bt % 25) * 32, d0v = (bt / 25) * 32;
        #pragma unroll
        for (int r = 0; r < 32; r += 8) {
            int d = d0v + ty8 + r, gk = gk0 + tx;
            ttile[ty8 + r][tx] = (gk < KKT * 16) ? wspan[(size_t)d * (KKT * 16) + gk] : 0.f;
        }
        __syncthreads();
        #pragma unroll
        for (int r = 0; r < 32; r += 8) {
            int gk = gk0 + ty8 + r, d = d0v + tx;
            if (gk < KKT * 16) g_wsT[(size_t)gk * CR + d] = ttile[tx][ty8 + r];
        }
        return;
    }

    const int pix0 = blockIdx.x * RPXB;
    const int dt = t & 15, mt = t >> 4;
    const int d0 = dt * 4;

    float4 acc[4];
    #pragma unroll
    for (int i = 0; i < 4; ++i) acc[i] = make_float4(0.f, 0.f, 0.f, 0.f);

    for (int cb = 0; cb < 4; ++cb) {
        #pragma unroll
        for (int k = 0; k < 4; ++k) {
            int idx = t + k * 256;
            int p = idx >> 4, c = idx & 15;
            *(float4*)&s.xs[p][c * 4] =
                __ldg((const float4*)&x[(size_t)(pix0 + p) * CC + cb * 64 + c * 4]);
        }
        #pragma unroll
        for (int k = 0; k < 4; ++k) {
            int idx = t + k * 256;
            int r = idx >> 4, c = idx & 15;
            *(float4*)&s.ws[r][c * 4] =
                __ldg((const float4*)&wr[(size_t)(cb * 64 + r) * CR + c * 4]);
        }
        __syncthreads();
        #pragma unroll 4
        for (int c4 = 0; c4 < 16; ++c4) {
            float4 w0 = *(float4*)&s.ws[c4 * 4 + 0][d0];
            float4 w1 = *(float4*)&s.ws[c4 * 4 + 1][d0];
            float4 w2 = *(float4*)&s.ws[c4 * 4 + 2][d0];
            float4 w3 = *(float4*)&s.ws[c4 * 4 + 3][d0];
            #pragma unroll
            for (int i = 0; i < 4; ++i) {
                float4 a = *(float4*)&s.xs[mt * 4 + i][c4 * 4];
                acc[i].x += a.x*w0.x + a.y*w1.x + a.z*w2.x + a.w*w3.x;
                acc[i].y += a.x*w0.y + a.y*w1.y + a.z*w2.y + a.w*w3.y;
                acc[i].z += a.x*w0.z + a.y*w1.z + a.z*w2.z + a.w*w3.z;
                acc[i].w += a.x*w0.w + a.y*w1.w + a.z*w2.w + a.w*w3.w;
            }
        }
        __syncthreads();
    }
    float4 gm = __ldg((const float4*)&gamma[d0]);
    float4 bt4 = __ldg((const float4*)&beta[d0]);
    float4 mn = __ldg((const float4*)&mean[d0]);
    float4 vr = __ldg((const float4*)&var[d0]);
    float4 sc, bb2;
    sc.x = gm.x * rsqrtf(vr.x + 1e-3f); bb2.x = bt4.x - mn.x * sc.x;
    sc.y = gm.y * rsqrtf(vr.y + 1e-3f); bb2.y = bt4.y - mn.y * sc.y;
    sc.z = gm.z * rsqrtf(vr.z + 1e-3f); bb2.z = bt4.z - mn.z * sc.z;
    sc.w = gm.w * rsqrtf(vr.w + 1e-3f); bb2.w = bt4.w - mn.w * sc.w;
    #pragma unroll
    for (int i = 0; i < 4; ++i) {
        float4 v;
        v.x = fmaxf(acc[i].x * sc.x + bb2.x, 0.f);
        v.y = fmaxf(acc[i].y * sc.y + bb2.y, 0.f);
        v.z = fmaxf(acc[i].z * sc.z + bb2.z, 0.f);
        v.w = fmaxf(acc[i].w * sc.w + bb2.w, 0.f);
        *(float4*)&g_rs[(size_t)(pix0 + mt * 4 + i) * CR + d0] = v;
    }
}

// ------------------------------------------------ main
struct SmemM {
    float  rs[64][RSPD];          // 17408 B  [px][d]
    float4 xh4[2][4][NPOS];       // 25088 B  halo [buf][c4][pos], 1 group each
    float  kg[64][KGR];           // 14336 B  [px][kh*8+kw]
};                                // 56832 B -> 4 CTAs/SM (with <=64 regs)

__global__ __launch_bounds__(256, 4)
void inv_main(const float* __restrict__ x,
              const float* __restrict__ b_span,
              float* __restrict__ out) {
    extern __shared__ __align__(16) float smf[];
    SmemM& s = *reinterpret_cast<SmemM*>(smf);
    const int t = threadIdx.x;
    const int w0 = blockIdx.x * TILE, h0 = blockIdx.y * TILE;
    const int bb = blockIdx.z >> 1, ghalf = blockIdx.z & 1;
    const size_t pixbase = ((size_t)bb * HH + h0) * WWD + w0;

    // prologue: stage rs tile [64px][64d]
    #pragma unroll
    for (int k = 0; k < 4; ++k) {
        int i = t + k * 256;
        int px = i >> 4, c = i & 15;
        int py = px >> 3, pxl = px & 7;
        size_t pix = pixbase + (size_t)py * WWD + pxl;
        *(float4*)&s.rs[px][c * 4] = __ldg((const float4*)&g_rs[pix * CR + c * 4]);
    }
    // prologue: halo(group0) into buf 0
    for (int i = t; i < NPOS * 4; i += 256) {
        int pos = i >> 2, q = i & 3;
        int hh = pos / HALO, ww = pos - hh * HALO;
        int h = h0 + hh - 3, w = w0 + ww - 3;
        float4 v = make_float4(0.f, 0.f, 0.f, 0.f);
        if (h >= 0 && h < HH && w >= 0 && w < WWD)
            v = __ldg((const float4*)&x[(((size_t)bb * HH + h) * WWD + w) * CC
                                        + (ghalf * 8) * CGC + q * 4]);
        s.xh4[0][q][pos] = v;
    }
    __syncthreads();

    for (int it = 0; it < 8; ++it) {
        const int g = ghalf * 8 + it;
        const int buf = it & 1;

        // ---- P1: B3 span-GEMM (224 threads; warp = kh, warp-uniform w LDG) ----
        if (t < 224) {
            const int kgi = t >> 5;          // 0..6 == kh
            const int pq  = t & 31;          // px pair = (pq, pq+32)
            const int kbase = g * KKT + kgi * 7;
            const float* wrow = g_wsT + (size_t)kbase * CR;
            float acc0[7], acc1[7];
            #pragma unroll
            for (int j = 0; j < 7; ++j) {
                float bv = __ldg(&b_span[kbase + j]);
                acc0[j] = bv; acc1[j] = bv;
            }
            #pragma unroll 4
            for (int d4 = 0; d4 < 16; ++d4) {
                float4 r0 = *(float4*)&s.rs[pq][d4 * 4];
                float4 r1 = *(float4*)&s.rs[pq + 32][d4 * 4];
                #pragma unroll
                for (int j = 0; j < 7; ++j) {
                    float4 w4 = __ldg((const float4*)&wrow[j * CR + d4 * 4]);
                    acc0[j] += r0.x*w4.x + r0.y*w4.y + r0.z*w4.z + r0.w*w4.w;
                    acc1[j] += r1.x*w4.x + r1.y*w4.y + r1.z*w4.z + r1.w*w4.w;
                }
            }
            #pragma unroll
            for (int j = 0; j < 7; ++j) {
                s.kg[pq][kgi * 8 + j] = acc0[j];        // kh-major row of 8
                s.kg[pq + 32][kgi * 8 + j] = acc1[j];
            }
        }
        __syncthreads();

        // ---- P2: B4 involution (threads 0-127) || halo(g+1) (threads 128-255) ----
        if (t < 128) {
            const int c4 = t >> 5;           // warp-uniform channel quad
            const int pr = t & 31;
            const int py0 = (pr >> 3) * 2, pxl = pr & 7;
            const int px0 = py0 * 8 + pxl;
            float4 a0 = make_float4(0.f, 0.f, 0.f, 0.f);
            float4 a1 = make_float4(0.f, 0.f, 0.f, 0.f);
            const float4* xcol = &s.xh4[buf][c4][0];
            #pragma unroll
            for (int rr = 0; rr < 8; ++rr) {
                const int row = py0 + rr;
                float4 xw[7];
                #pragma unroll
                for (int kw = 0; kw < 7; ++kw)
                    xw[kw] = xcol[row * HALO + pxl + kw];
                if (rr <= 6) {
                    float4 ka = *(float4*)&s.kg[px0][rr * 8];
                    float4 kb = *(float4*)&s.kg[px0][rr * 8 + 4];
                    a0.x += ka.x*xw[0].x + ka.y*xw[1].x + ka.z*xw[2].x + ka.w*xw[3].x
                          + kb.x*xw[4].x + kb.y*xw[5].x + kb.z*xw[6].x;
                    a0.y += ka.x*xw[0].y + ka.y*xw[1].y + ka.z*xw[2].y + ka.w*xw[3].y
                          + kb.x*xw[4].y + kb.y*xw[5].y + kb.z*xw[6].y;
                    a0.z += ka.x*xw[0].z + ka.y*xw[1].z + ka.z*xw[2].z + ka.w*xw[3].z
                          + kb.x*xw[4].z + kb.y*xw[5].z + kb.z*xw[6].z;
                    a0.w += ka.x*xw[0].w + ka.y*xw[1].w + ka.z*xw[2].w + ka.w*xw[3].w
                          + kb.x*xw[4].w + kb.y*xw[5].w + kb.z*xw[6].w;
                }
                if (rr >= 1) {
                    float4 ka = *(float4*)&s.kg[px0 + 8][(rr - 1) * 8];
                    float4 kb = *(float4*)&s.kg[px0 + 8][(rr - 1) * 8 + 4];
                    a1.x += ka.x*xw[0].x + ka.y*xw[1].x + ka.z*xw[2].x + ka.w*xw[3].x
                          + kb.x*xw[4].x + kb.y*xw[5].x + kb.z*xw[6].x;
                    a1.y += ka.x*xw[0].y + ka.y*xw[1].y + ka.z*xw[2].y + ka.w*xw[3].y
                          + kb.x*xw[4].y + kb.y*xw[5].y + kb.z*xw[6].y;
                    a1.z += ka.x*xw[0].z + ka.y*xw[1].z + ka.z*xw[2].z + ka.w*xw[3].z
                          + kb.x*xw[4].z + kb.y*xw[5].z + kb.z*xw[6].z;
                    a1.w += ka.x*xw[0].w + ka.y*xw[1].w + ka.z*xw[2].w + ka.w*xw[3].w
                          + kb.x*xw[4].w + kb.y*xw[5].w + kb.z*xw[6].w;
                }
            }
            size_t o = (pixbase + (size_t)py0 * WWD + pxl) * CC + g * CGC + c4 * 4;
            *(float4*)&out[o] = a0;
            *(float4*)&out[o + (size_t)WWD * CC] = a1;
        } else if (it < 7) {
            for (int i = t - 128; i < NPOS * 4; i += 128) {
                int pos = i >> 2, q = i & 3;
                int hh = pos / HALO, ww = pos - hh * HALO;
                int h = h0 + hh - 3, w = w0 + ww - 3;
                float4 v = make_float4(0.f, 0.f, 0.f, 0.f);
                if (h >= 0 && h < HH && w >= 0 && w < WWD)
                    v = __ldg((const float4*)&x[(((size_t)bb * HH + h) * WWD + w) * CC
                                                + (g + 1) * CGC + q * 4]);
                s.xh4[buf ^ 1][q][pos] = v;
            }
        }
        __syncthreads();
    }
}

// ------------------------------------------------ launch
extern "C" void kernel_launch(void* const* d_in, const int* in_sizes, int n_in,
                              void* d_out, int out_size) {
    (void)in_sizes; (void)n_in; (void)out_size;
    const float* x        = (const float*)d_in[0];
    const float* w_reduce = (const float*)d_in[1];
    const float* gamma    = (const float*)d_in[2];
    const float* beta     = (const float*)d_in[3];
    const float* mean     = (const float*)d_in[4];
    const float* var      = (const float*)d_in[5];
    const float* w_span   = (const float*)d_in[6];
    const float* b_span   = (const float*)d_in[7];
    float* out = (float*)d_out;

    cudaFuncSetAttribute(rs_kernel, cudaFuncAttributeMaxDynamicSharedMemorySize,
                         (int)sizeof(SmemR));
    cudaFuncSetAttribute(inv_main, cudaFuncAttributeMaxDynamicSharedMemorySize,
                         (int)sizeof(SmemM));

    rs_kernel<<<NRSBLK + 50, 256, sizeof(SmemR)>>>(x, w_reduce, gamma, beta,
                                                   mean, var, w_span);
    dim3 grid(WWD / TILE, HH / TILE, 8);   // (7, 7, 8) = 392 CTAs
    inv_main<<<grid, 256, sizeof(SmemM)>>>(x, b_span, out);
}

// round 10
// speedup vs baseline: 1.2214x; 1.2214x over previous
#include <cuda_runtime.h>

// Involution: B=4, H=W=56, C=256, Cr=64, G=16, Cg=16, K=7, pad=3
// Round 9: best-of recombination — R7 inv_main (77.4us measured) + R8 rs_kernel
// (~14.5us measured). No structural changes.

#define HH 56
#define WWD 56
#define CC 256
#define CR 64
#define NG 16
#define CGC 16
#define KKT 49
#define NPIXT 12544
#define TILE 8
#define HALO 14
#define NPOS 196         // 14*14
#define KGP 50
#define RSPD 68

__device__ __align__(16) float g_wsT[NG * KKT * CR];   // [g*49+k][d]
__device__ __align__(16) float g_rs[(size_t)NPIXT * CR];

// ------------------------------------------------ rs GEMM (+ overlapped transpose)
#define RPXB 64
#define NRSBLK 196
struct SmemR {
    float xs[RPXB][68];   // 17408 B
    float ws[CR][CR];     // 16384 B
};

__global__ __launch_bounds__(256)
void rs_kernel(const float* __restrict__ x,
               const float* __restrict__ wr,
               const float* __restrict__ gamma,
               const float* __restrict__ beta,
               const float* __restrict__ mean,
               const float* __restrict__ var,
               const float* __restrict__ wspan) {
    extern __shared__ __align__(16) float smr[];
    SmemR& s = *reinterpret_cast<SmemR*>(smr);
    const int t = threadIdx.x;

    if (blockIdx.x >= NRSBLK) {
        __shared__ float ttile[32][33];
        const int bt = blockIdx.x - NRSBLK;          // 0..49
        const int tx = t & 31, ty8 = t >> 5;
        const int gk0 = (bt % 25) * 32, d0v = (bt / 25) * 32;
        #pragma unroll
        for (int r = 0; r < 32; r += 8) {
            int d = d0v + ty8 + r, gk = gk0 + tx;
            ttile[ty8 + r][tx] = (gk < KKT * NG) ? wspan[(size_t)d * (KKT * NG) + gk] : 0.f;
        }
        __syncthreads();
        #pragma unroll
        for (int r = 0; r < 32; r += 8) {
            int gk = gk0 + ty8 + r, d = d0v + tx;
            if (gk < KKT * NG) g_wsT[(size_t)gk * CR + d] = ttile[tx][ty8 + r];
        }
        return;
    }

    const int pix0 = blockIdx.x * RPXB;
    const int dt = t & 15, mt = t >> 4;
    const int d0 = dt * 4;

    float4 acc[4];
    #pragma unroll
    for (int i = 0; i < 4; ++i) acc[i] = make_float4(0.f, 0.f, 0.f, 0.f);

    for (int cb = 0; cb < 4; ++cb) {
        #pragma unroll
        for (int k = 0; k < 4; ++k) {
            int idx = t + k * 256;
            int p = idx >> 4, c = idx & 15;
            *(float4*)&s.xs[p][c * 4] =
                __ldg((const float4*)&x[(size_t)(pix0 + p) * CC + cb * 64 + c * 4]);
        }
        #pragma unroll
        for (int k = 0; k < 4; ++k) {
            int idx = t + k * 256;
            int r = idx >> 4, c = idx & 15;
            *(float4*)&s.ws[r][c * 4] =
                __ldg((const float4*)&wr[(size_t)(cb * 64 + r) * CR + c * 4]);
        }
        __syncthreads();
        #pragma unroll 4
        for (int c4 = 0; c4 < 16; ++c4) {
            float4 w0 = *(float4*)&s.ws[c4 * 4 + 0][d0];
            float4 w1 = *(float4*)&s.ws[c4 * 4 + 1][d0];
            float4 w2 = *(float4*)&s.ws[c4 * 4 + 2][d0];
            float4 w3 = *(float4*)&s.ws[c4 * 4 + 3][d0];
            #pragma unroll
            for (int i = 0; i < 4; ++i) {
                float4 a = *(float4*)&s.xs[mt * 4 + i][c4 * 4];
                acc[i].x += a.x*w0.x + a.y*w1.x + a.z*w2.x + a.w*w3.x;
                acc[i].y += a.x*w0.y + a.y*w1.y + a.z*w2.y + a.w*w3.y;
                acc[i].z += a.x*w0.z + a.y*w1.z + a.z*w2.z + a.w*w3.z;
                acc[i].w += a.x*w0.w + a.y*w1.w + a.z*w2.w + a.w*w3.w;
            }
        }
        __syncthreads();
    }
    float4 gm = __ldg((const float4*)&gamma[d0]);
    float4 bt4 = __ldg((const float4*)&beta[d0]);
    float4 mn = __ldg((const float4*)&mean[d0]);
    float4 vr = __ldg((const float4*)&var[d0]);
    float4 sc, bb2;
    sc.x = gm.x * rsqrtf(vr.x + 1e-3f); bb2.x = bt4.x - mn.x * sc.x;
    sc.y = gm.y * rsqrtf(vr.y + 1e-3f); bb2.y = bt4.y - mn.y * sc.y;
    sc.z = gm.z * rsqrtf(vr.z + 1e-3f); bb2.z = bt4.z - mn.z * sc.z;
    sc.w = gm.w * rsqrtf(vr.w + 1e-3f); bb2.w = bt4.w - mn.w * sc.w;
    #pragma unroll
    for (int i = 0; i < 4; ++i) {
        float4 v;
        v.x = fmaxf(acc[i].x * sc.x + bb2.x, 0.f);
        v.y = fmaxf(acc[i].y * sc.y + bb2.y, 0.f);
        v.z = fmaxf(acc[i].z * sc.z + bb2.z, 0.f);
        v.w = fmaxf(acc[i].w * sc.w + bb2.w, 0.f);
        *(float4*)&g_rs[(size_t)(pix0 + mt * 4 + i) * CR + d0] = v;
    }
}

// ------------------------------------------------ main (R7 structure, 77.4us measured)
struct SmemM {
    float  rs[64][RSPD];          // 17408 B  [px][d]
    float4 xh4[2][4][NPOS];       // 25088 B  halo, [g][c4][pos], single buffer
    float  kg[2][64][KGP];        // 25600 B  [g][px][k]
};                                // 68096 B -> 3 CTAs/SM

__global__ __launch_bounds__(256, 3)
void inv_main(const float* __restrict__ x,
              const float* __restrict__ b_span,
              float* __restrict__ out) {
    extern __shared__ __align__(16) float smf[];
    SmemM& s = *reinterpret_cast<SmemM*>(smf);
    const int t = threadIdx.x;
    const int w0 = blockIdx.x * TILE, h0 = blockIdx.y * TILE;
    const int bb = blockIdx.z >> 1, ghalf = blockIdx.z & 1;
    const size_t pixbase = ((size_t)bb * HH + h0) * WWD + w0;

    // prologue: stage rs tile [64 px][64 d]
    for (int i = t; i < 64 * 16; i += 256) {
        int px = i >> 4, c = i & 15;
        int py = px >> 3, pxl = px & 7;
        size_t pix = pixbase + (size_t)py * WWD + pxl;
        *(float4*)&s.rs[px][c * 4] = __ldg((const float4*)&g_rs[pix * CR + c * 4]);
    }
    __syncthreads();

    for (int it = 0; it < 4; ++it) {
        const int gA = ghalf * 8 + it * 2;

        // ---- phase 1: halo load (all threads, LDG hidden behind B3 FMA) ----
        for (int i = t; i < 2 * NPOS * 4; i += 256) {
            int g, rem;
            if (i >= 784) { g = 1; rem = i - 784; } else { g = 0; rem = i; }
            int pos = rem >> 2, q = rem & 3;
            int hh = pos / HALO, ww = pos - hh * HALO;
            int h = h0 + hh - 3, w = w0 + ww - 3;
            float4 v = make_float4(0.f, 0.f, 0.f, 0.f);
            if (h >= 0 && h < HH && w >= 0 && w < WWD)
                v = __ldg((const float4*)&x[(((size_t)bb * HH + h) * WWD + w) * CC
                                            + (gA + g) * CGC + q * 4]);
            s.xh4[g][q][pos] = v;
        }

        // ---- B3: kg[g][px][k] = rs[px][:] . wsT[g][k][:] + bias (224 thr) ----
        if (t < 224) {
            const int g = t / 112, r = t - g * 112;
            const int quad = r & 15, kgi = r >> 4;   // 16 quads x 7 k-groups
            const int k0 = kgi * 7;
            const float* wrow = g_wsT + (size_t)((gA + g) * KKT + k0) * CR;
            const float* bs = b_span + (gA + g) * KKT + k0;
            float acc[4][7];
            #pragma unroll
            for (int j = 0; j < 7; ++j) {
                float bv = __ldg(&bs[j]);
                acc[0][j] = bv; acc[1][j] = bv; acc[2][j] = bv; acc[3][j] = bv;
            }
            #pragma unroll 4
            for (int d4 = 0; d4 < 16; ++d4) {
                float4 r0 = *(float4*)&s.rs[quad +  0][d4 * 4];
                float4 r1 = *(float4*)&s.rs[quad + 16][d4 * 4];
                float4 r2 = *(float4*)&s.rs[quad + 32][d4 * 4];
                float4 r3 = *(float4*)&s.rs[quad + 48][d4 * 4];
                #pragma unroll
                for (int j = 0; j < 7; ++j) {
                    float4 w4 = __ldg((const float4*)&wrow[j * CR + d4 * 4]);
                    acc[0][j] += r0.x*w4.x + r0.y*w4.y + r0.z*w4.z + r0.w*w4.w;
                    acc[1][j] += r1.x*w4.x + r1.y*w4.y + r1.z*w4.z + r1.w*w4.w;
                    acc[2][j] += r2.x*w4.x + r2.y*w4.y + r2.z*w4.z + r2.w*w4.w;
                    acc[3][j] += r3.x*w4.x + r3.y*w4.y + r3.z*w4.z + r3.w*w4.w;
                }
            }
            #pragma unroll
            for (int i = 0; i < 4; ++i)
                #pragma unroll
                for (int j = 0; j < 7; ++j)
                    s.kg[g][quad + 16 * i][k0 + j] = acc[i][j];
        }
        __syncthreads();

        // ---- B4: 2-px column per thread, 8-row sliding window (256 thr) ----
        {
            const int g = t >> 7, r = t & 127;
            const int pyq = r >> 5, rr = r & 31;
            const int c4 = rr >> 3, pxl = rr & 7;   // quarter-warp: same c4, pxl 0-7
            const int py0 = pyq * 2;
            float4 a0 = make_float4(0.f, 0.f, 0.f, 0.f);
            float4 a1 = make_float4(0.f, 0.f, 0.f, 0.f);
            const float4* xcol = &s.xh4[g][c4][0];
            const float* kg0 = &s.kg[g][py0 * 8 + pxl][0];
            const float* kg1 = &s.kg[g][(py0 + 1) * 8 + pxl][0];
            #pragma unroll
            for (int rr8 = 0; rr8 < 8; ++rr8) {
                const int row = py0 + rr8;
                float4 xw[7];
                #pragma unroll
                for (int kw = 0; kw < 7; ++kw)
                    xw[kw] = xcol[row * HALO + pxl + kw];
                if (rr8 <= 6) {
                    const float* kgr = kg0 + rr8 * 7;
                    #pragma unroll
                    for (int kw = 0; kw < 7; ++kw) {
                        float kv = kgr[kw];
                        a0.x += kv * xw[kw].x; a0.y += kv * xw[kw].y;
                        a0.z += kv * xw[kw].z; a0.w += kv * xw[kw].w;
                    }
                }
                if (rr8 >= 1) {
                    const float* kgr = kg1 + (rr8 - 1) * 7;
                    #pragma unroll
                    for (int kw = 0; kw < 7; ++kw) {
                        float kv = kgr[kw];
                        a1.x += kv * xw[kw].x; a1.y += kv * xw[kw].y;
                        a1.z += kv * xw[kw].z; a1.w += kv * xw[kw].w;
                    }
                }
            }
            size_t o = (pixbase + (size_t)py0 * WWD + pxl) * CC + (gA + g) * CGC + c4 * 4;
            *(float4*)&out[o] = a0;
            *(float4*)&out[o + (size_t)WWD * CC] = a1;
        }
        __syncthreads();   // protect xh/kg before next iteration overwrites
    }
}

// ------------------------------------------------ launch
extern "C" void kernel_launch(void* const* d_in, const int* in_sizes, int n_in,
                              void* d_out, int out_size) {
    (void)in_sizes; (void)n_in; (void)out_size;
    const float* x        = (const float*)d_in[0];
    const float* w_reduce = (const float*)d_in[1];
    const float* gamma    = (const float*)d_in[2];
    const float* beta     = (const float*)d_in[3];
    const float* mean     = (const float*)d_in[4];
    const float* var      = (const float*)d_in[5];
    const float* w_span   = (const float*)d_in[6];
    const float* b_span   = (const float*)d_in[7];
    float* out = (float*)d_out;

    cudaFuncSetAttribute(rs_kernel, cudaFuncAttributeMaxDynamicSharedMemorySize,
                         (int)sizeof(SmemR));
    cudaFuncSetAttribute(inv_main, cudaFuncAttributeMaxDynamicSharedMemorySize,
                         (int)sizeof(SmemM));

    rs_kernel<<<NRSBLK + 50, 256, sizeof(SmemR)>>>(x, w_reduce, gamma, beta,
                                                   mean, var, w_span);
    dim3 grid(WWD / TILE, HH / TILE, 8);   // (7, 7, 8) = 392 CTAs
    inv_main<<<grid, 256, sizeof(SmemM)>>>(x, b_span, out);
}

// round 11
// speedup vs baseline: 1.2433x; 1.0179x over previous
#include <cuda_runtime.h>

// Involution: B=4, H=W=56, C=256, Cr=64, G=16, Cg=16, K=7, pad=3
// Round 10: R9 skeleton + f32x2 B3 (transposed rs, pixel-pair lds64,
// 14 u64 accumulators, mov-packed weights, kg pad 49).

#define HH 56
#define WWD 56
#define CC 256
#define CR 64
#define NG 16
#define CGC 16
#define KKT 49
#define NPIXT 12544
#define TILE 8
#define HALO 14
#define NPOS 196
#define KGP 49
#define RSPD 66

using u64 = unsigned long long;

__device__ __align__(16) float g_wsT[NG * KKT * CR];   // [g*49+k][d]
__device__ __align__(16) float g_rs[(size_t)NPIXT * CR];

__device__ __forceinline__ u64 pack2(float lo, float hi) {
    u64 r; asm("mov.b64 %0,{%1,%2};" : "=l"(r) : "f"(lo), "f"(hi)); return r;
}
__device__ __forceinline__ u64 fma2(u64 a, u64 b, u64 c) {
    u64 d; asm("fma.rn.f32x2 %0,%1,%2,%3;" : "=l"(d) : "l"(a), "l"(b), "l"(c)); return d;
}
__device__ __forceinline__ void unpack2(u64 v, float& lo, float& hi) {
    asm("mov.b64 {%0,%1},%2;" : "=f"(lo), "=f"(hi) : "l"(v));
}
__device__ __forceinline__ u64 lds64(unsigned a) {
    u64 v; asm("ld.shared.b64 %0,[%1];" : "=l"(v) : "r"(a)); return v;
}

// ------------------------------------------------ rs GEMM (+ overlapped transpose)
#define RPXB 64
#define NRSBLK 196
struct SmemR {
    float xs[RPXB][68];
    float ws[CR][CR];
};

__global__ __launch_bounds__(256)
void rs_kernel(const float* __restrict__ x,
               const float* __restrict__ wr,
               const float* __restrict__ gamma,
               const float* __restrict__ beta,
               const float* __restrict__ mean,
               const float* __restrict__ var,
               const float* __restrict__ wspan) {
    extern __shared__ __align__(16) float smr[];
    SmemR& s = *reinterpret_cast<SmemR*>(smr);
    const int t = threadIdx.x;

    if (blockIdx.x >= NRSBLK) {
        __shared__ float ttile[32][33];
        const int bt = blockIdx.x - NRSBLK;
        const int tx = t & 31, ty8 = t >> 5;
        const int gk0 = (bt % 25) * 32, d0v = (bt / 25) * 32;
        #pragma unroll
        for (int r = 0; r < 32; r += 8) {
            int d = d0v + ty8 + r, gk = gk0 + tx;
            ttile[ty8 + r][tx] = (gk < KKT * NG) ? wspan[(size_t)d * (KKT * NG) + gk] : 0.f;
        }
        __syncthreads();
        #pragma unroll
        for (int r = 0; r < 32; r += 8) {
            int gk = gk0 + ty8 + r, d = d0v + tx;
            if (gk < KKT * NG) g_wsT[(size_t)gk * CR + d] = ttile[tx][ty8 + r];
        }
        return;
    }

    const int pix0 = blockIdx.x * RPXB;
    const int dt = t & 15, mt = t >> 4;
    const int d0 = dt * 4;

    float4 acc[4];
    #pragma unroll
    for (int i = 0; i < 4; ++i) acc[i] = make_float4(0.f, 0.f, 0.f, 0.f);

    for (int cb = 0; cb < 4; ++cb) {
        #pragma unroll
        for (int k = 0; k < 4; ++k) {
            int idx = t + k * 256;
            int p = idx >> 4, c = idx & 15;
            *(float4*)&s.xs[p][c * 4] =
                __ldg((const float4*)&x[(size_t)(pix0 + p) * CC + cb * 64 + c * 4]);
        }
        #pragma unroll
        for (int k = 0; k < 4; ++k) {
            int idx = t + k * 256;
            int r = idx >> 4, c = idx & 15;
            *(float4*)&s.ws[r][c * 4] =
                __ldg((const float4*)&wr[(size_t)(cb * 64 + r) * CR + c * 4]);
        }
        __syncthreads();
        #pragma unroll 4
        for (int c4 = 0; c4 < 16; ++c4) {
            float4 w0 = *(float4*)&s.ws[c4 * 4 + 0][d0];
            float4 w1 = *(float4*)&s.ws[c4 * 4 + 1][d0];
            float4 w2 = *(float4*)&s.ws[c4 * 4 + 2][d0];
            float4 w3 = *(float4*)&s.ws[c4 * 4 + 3][d0];
            #pragma unroll
            for (int i = 0; i < 4; ++i) {
                float4 a = *(float4*)&s.xs[mt * 4 + i][c4 * 4];
                acc[i].x += a.x*w0.x + a.y*w1.x + a.z*w2.x + a.w*w3.x;
                acc[i].y += a.x*w0.y + a.y*w1.y + a.z*w2.y + a.w*w3.y;
                acc[i].z += a.x*w0.z + a.y*w1.z + a.z*w2.z + a.w*w3.z;
                acc[i].w += a.x*w0.w + a.y*w1.w + a.z*w2.w + a.w*w3.w;
            }
        }
        __syncthreads();
    }
    float4 gm = __ldg((const float4*)&gamma[d0]);
    float4 bt4 = __ldg((const float4*)&beta[d0]);
    float4 mn = __ldg((const float4*)&mean[d0]);
    float4 vr = __ldg((const float4*)&var[d0]);
    float4 sc, bb2;
    sc.x = gm.x * rsqrtf(vr.x + 1e-3f); bb2.x = bt4.x - mn.x * sc.x;
    sc.y = gm.y * rsqrtf(vr.y + 1e-3f); bb2.y = bt4.y - mn.y * sc.y;
    sc.z = gm.z * rsqrtf(vr.z + 1e-3f); bb2.z = bt4.z - mn.z * sc.z;
    sc.w = gm.w * rsqrtf(vr.w + 1e-3f); bb2.w = bt4.w - mn.w * sc.w;
    #pragma unroll
    for (int i = 0; i < 4; ++i) {
        float4 v;
        v.x = fmaxf(acc[i].x * sc.x + bb2.x, 0.f);
        v.y = fmaxf(acc[i].y * sc.y + bb2.y, 0.f);
        v.z = fmaxf(acc[i].z * sc.z + bb2.z, 0.f);
        v.w = fmaxf(acc[i].w * sc.w + bb2.w, 0.f);
        *(float4*)&g_rs[(size_t)(pix0 + mt * 4 + i) * CR + d0] = v;
    }
}

// ------------------------------------------------ main
struct SmemM {
    float  rsP[CR][RSPD];         // 16896 B  rs transposed [d][px]
    float4 xh4[2][4][NPOS];       // 25088 B  halo [g][c4][pos]
    float  kg[2][64][KGP];        // 25088 B  [g][px][k], pad 49 (odd)
};                                // 67072 B -> 3 CTAs/SM

__global__ __launch_bounds__(256, 3)
void inv_main(const float* __restrict__ x,
              const float* __restrict__ b_span,
              float* __restrict__ out) {
    extern __shared__ __align__(16) float smf[];
    SmemM& s = *reinterpret_cast<SmemM*>(smf);
    const int t = threadIdx.x;
    const int w0 = blockIdx.x * TILE, h0 = blockIdx.y * TILE;
    const int bb = blockIdx.z >> 1, ghalf = blockIdx.z & 1;
    const size_t pixbase = ((size_t)bb * HH + h0) * WWD + w0;

    // prologue: stage rs transposed [d][px]; lanes -> consecutive px (STS clean)
    #pragma unroll
    for (int k = 0; k < 4; ++k) {
        int i = t + k * 256;
        int px = i & 63, c = i >> 6;           // c 0..15
        int py = px >> 3, pxl = px & 7;
        size_t pix = pixbase + (size_t)py * WWD + pxl;
        float4 v = __ldg((const float4*)&g_rs[pix * CR + c * 4]);
        s.rsP[c * 4 + 0][px] = v.x;
        s.rsP[c * 4 + 1][px] = v.y;
        s.rsP[c * 4 + 2][px] = v.z;
        s.rsP[c * 4 + 3][px] = v.w;
    }
    __syncthreads();

    const unsigned rs_base = (unsigned)__cvta_generic_to_shared(&s.rsP[0][0]);

    for (int it = 0; it < 4; ++it) {
        const int gA = ghalf * 8 + it * 2;

        // ---- phase 1: halo load (all threads; LDG hidden behind B3 FMA) ----
        for (int i = t; i < 2 * NPOS * 4; i += 256) {
            int g, rem;
            if (i >= 784) { g = 1; rem = i - 784; } else { g = 0; rem = i; }
            int pos = rem >> 2, q = rem & 3;
            int hh = pos / HALO, ww = pos - hh * HALO;
            int h = h0 + hh - 3, w = w0 + ww - 3;
            float4 v = make_float4(0.f, 0.f, 0.f, 0.f);
            if (h >= 0 && h < HH && w >= 0 && w < WWD)
                v = __ldg((const float4*)&x[(((size_t)bb * HH + h) * WWD + w) * CC
                                            + (gA + g) * CGC + q * 4]);
            s.xh4[g][q][pos] = v;
        }

        // ---- B3: kg = rs @ wsT + bias, f32x2 over pixel pairs (224 thr) ----
        if (t < 224) {
            const int g = t / 112, r = t - g * 112;
            const int pp = r & 15, kgi = r >> 4;       // pair slots pp, pp+16
            const int k0 = kgi * 7;
            const int gg = gA + g;
            const float* wrow = g_wsT + (size_t)(gg * KKT + k0) * CR;
            const float* bs = b_span + gg * KKT + k0;
            u64 acc2[2][7];
            #pragma unroll
            for (int j = 0; j < 7; ++j) {
                float bv = __ldg(&bs[j]);
                u64 b2 = pack2(bv, bv);
                acc2[0][j] = b2; acc2[1][j] = b2;
            }
            const unsigned o0 = (unsigned)(2 * pp) * 4u;
            const unsigned o1 = (unsigned)(2 * (pp + 16)) * 4u;
            #pragma unroll 2
            for (int d4 = 0; d4 < 16; ++d4) {
                u64 ra[4], rb[4];
                #pragma unroll
                for (int dd = 0; dd < 4; ++dd) {
                    unsigned rowa = rs_base + (unsigned)((d4 * 4 + dd) * RSPD) * 4u;
                    ra[dd] = lds64(rowa + o0);
                    rb[dd] = lds64(rowa + o1);
                }
                #pragma unroll
                for (int j = 0; j < 7; ++j) {
                    float4 w4 = __ldg((const float4*)&wrow[j * CR + d4 * 4]);
                    u64 w2;
                    w2 = pack2(w4.x, w4.x);
                    acc2[0][j] = fma2(ra[0], w2, acc2[0][j]);
                    acc2[1][j] = fma2(rb[0], w2, acc2[1][j]);
                    w2 = pack2(w4.y, w4.y);
                    acc2[0][j] = fma2(ra[1], w2, acc2[0][j]);
                    acc2[1][j] = fma2(rb[1], w2, acc2[1][j]);
                    w2 = pack2(w4.z, w4.z);
                    acc2[0][j] = fma2(ra[2], w2, acc2[0][j]);
                    acc2[1][j] = fma2(rb[2], w2, acc2[1][j]);
                    w2 = pack2(w4.w, w4.w);
                    acc2[0][j] = fma2(ra[3], w2, acc2[0][j]);
                    acc2[1][j] = fma2(rb[3], w2, acc2[1][j]);
                }
            }
            #pragma unroll
            for (int i = 0; i < 2; ++i) {
                const int px = 2 * (pp + 16 * i);
                #pragma unroll
                for (int j = 0; j < 7; ++j) {
                    float lo, hi;
                    unpack2(acc2[i][j], lo, hi);
                    s.kg[g][px][k0 + j] = lo;
                    s.kg[g][px + 1][k0 + j] = hi;
                }
            }
        }
        __syncthreads();

        // ---- B4: 2-px column per thread, 8-row sliding window (256 thr) ----
        {
            const int g = t >> 7, r = t & 127;
            const int pyq = r >> 5, rr = r & 31;
            const int c4 = rr >> 3, pxl = rr & 7;
            const int py0 = pyq * 2;
            float4 a0 = make_float4(0.f, 0.f, 0.f, 0.f);
            float4 a1 = make_float4(0.f, 0.f, 0.f, 0.f);
            const float4* xcol = &s.xh4[g][c4][0];
            const float* kg0 = &s.kg[g][py0 * 8 + pxl][0];
            const float* kg1 = &s.kg[g][(py0 + 1) * 8 + pxl][0];
            #pragma unroll
            for (int rr8 = 0; rr8 < 8; ++rr8) {
                const int row = py0 + rr8;
                float4 xw[7];
                #pragma unroll
                for (int kw = 0; kw < 7; ++kw)
                    xw[kw] = xcol[row * HALO + pxl + kw];
                if (rr8 <= 6) {
                    const float* kgr = kg0 + rr8 * 7;
                    #pragma unroll
                    for (int kw = 0; kw < 7; ++kw) {
                        float kv = kgr[kw];
                        a0.x += kv * xw[kw].x; a0.y += kv * xw[kw].y;
                        a0.z += kv * xw[kw].z; a0.w += kv * xw[kw].w;
                    }
                }
                if (rr8 >= 1) {
                    const float* kgr = kg1 + (rr8 - 1) * 7;
                    #pragma unroll
                    for (int kw = 0; kw < 7; ++kw) {
                        float kv = kgr[kw];
                        a1.x += kv * xw[kw].x; a1.y += kv * xw[kw].y;
                        a1.z += kv * xw[kw].z; a1.w += kv * xw[kw].w;
                    }
                }
            }
            size_t o = (pixbase + (size_t)py0 * WWD + pxl) * CC + (gA + g) * CGC + c4 * 4;
            *(float4*)&out[o] = a0;
            *(float4*)&out[o + (size_t)WWD * CC] = a1;
        }
        __syncthreads();
    }
}

// ------------------------------------------------ launch
extern "C" void kernel_launch(void* const* d_in, const int* in_sizes, int n_in,
                              void* d_out, int out_size) {
    (void)in_sizes; (void)n_in; (void)out_size;
    const float* x        = (const float*)d_in[0];
    const float* w_reduce = (const float*)d_in[1];
    const float* gamma    = (const float*)d_in[2];
    const float* beta     = (const float*)d_in[3];
    const float* mean     = (const float*)d_in[4];
    const float* var      = (const float*)d_in[5];
    const float* w_span   = (const float*)d_in[6];
    const float* b_span   = (const float*)d_in[7];
    float* out = (float*)d_out;

    cudaFuncSetAttribute(rs_kernel, cudaFuncAttributeMaxDynamicSharedMemorySize,
                         (int)sizeof(SmemR));
    cudaFuncSetAttribute(inv_main, cudaFuncAttributeMaxDynamicSharedMemorySize,
                         (int)sizeof(SmemM));

    rs_kernel<<<NRSBLK + 50, 256, sizeof(SmemR)>>>(x, w_reduce, gamma, beta,
                                                   mean, var, w_span);
    dim3 grid(WWD / TILE, HH / TILE, 8);   // (7, 7, 8) = 392 CTAs
    inv_main<<<grid, 256, sizeof(SmemM)>>>(x, b_span, out);
}